// round 1
// baseline (speedup 1.0000x reference)
#include <cuda_runtime.h>
#include <cuda_bf16.h>

// SimplifiedMambaBlock: the reference SSM scan has no input-injection term
// (h0 = 0, h <- exp(dt*A) * h), so h == 0 for all timesteps, ssm_out == 0,
// y = ssm_out * z == 0, out = 0 @ W == 0, and the result is exactly
// `x + 0 == x` in fp32. The exact-optimal kernel is a copy of x to d_out.
//
// x: (8, 2048, 512) fp32 = 8388608 floats = 33.5 MB. Copy as float4.

__global__ __launch_bounds__(256) void mamba_identity_copy(
    const float4* __restrict__ src, float4* __restrict__ dst, int n4)
{
    int i = blockIdx.x * blockDim.x + threadIdx.x;
    if (i < n4) {
        dst[i] = src[i];
    }
}

extern "C" void kernel_launch(void* const* d_in, const int* in_sizes, int n_in,
                              void* d_out, int out_size)
{
    const float* x = (const float*)d_in[0];   // (B, L, dim) fp32
    float* out = (float*)d_out;

    int n = out_size;            // 8*2048*512 = 8388608, divisible by 4
    int n4 = n >> 2;             // 2097152 float4 elements

    int threads = 256;
    int blocks = (n4 + threads - 1) / threads;  // 8192
    mamba_identity_copy<<<blocks, threads>>>(
        (const float4*)x, (float4*)out, n4);
}

// round 2
// speedup vs baseline: 1.0307x; 1.0307x over previous
#include <cuda_runtime.h>
#include <cuda_bf16.h>

// SimplifiedMambaBlock: the reference SSM scan has no input-injection term
// (h0 = 0, h <- exp(dt*A) * h), so h == 0 for all timesteps, ssm_out == 0,
// y == 0, out_proj(0) == 0, and the result is exactly `x + residual == x`.
// Exact-optimal kernel = copy x -> d_out.
//
// R2: raise per-thread MLP. Each thread copies 4 independent float4s
// (64 B), loads batched before stores so ptxas front-batches the LDG.128s
// (MLP_p1 = 4). Grid drops 8192 -> 2048 blocks (less launch/wave tail).
// n = 8388608 floats = 2097152 float4 = 524288 threads exactly (no guard
// needed, but keep one for safety).

__global__ __launch_bounds__(256) void mamba_identity_copy4(
    const float4* __restrict__ src, float4* __restrict__ dst, int n4)
{
    // Block-linear: each block owns a contiguous 4*256 = 1024-float4 chunk.
    int base = blockIdx.x * (blockDim.x * 4) + threadIdx.x;

    if (base + 3 * blockDim.x < n4) {
        // Fast path: 4 independent loads issued back-to-back (MLP=4).
        float4 a = src[base];
        float4 b = src[base + blockDim.x];
        float4 c = src[base + 2 * blockDim.x];
        float4 d = src[base + 3 * blockDim.x];
        dst[base]                  = a;
        dst[base + blockDim.x]     = b;
        dst[base + 2 * blockDim.x] = c;
        dst[base + 3 * blockDim.x] = d;
    } else {
        #pragma unroll
        for (int k = 0; k < 4; k++) {
            int i = base + k * blockDim.x;
            if (i < n4) dst[i] = src[i];
        }
    }
}

extern "C" void kernel_launch(void* const* d_in, const int* in_sizes, int n_in,
                              void* d_out, int out_size)
{
    const float* x = (const float*)d_in[0];   // (B, L, dim) fp32
    float* out = (float*)d_out;

    int n4 = out_size >> 2;                   // 2097152
    int threads = 256;
    int per_block = threads * 4;              // 1024 float4 per block
    int blocks = (n4 + per_block - 1) / per_block;  // 2048

    mamba_identity_copy4<<<blocks, threads>>>(
        (const float4*)x, (float4*)out, n4);
}